// round 7
// baseline (speedup 1.0000x reference)
#include <cuda_runtime.h>
#include <cuda_bf16.h>
#include <cstdint>

#define HDIM 1024
#define VDIM 128
#define NS   7          // K-splits: 3 chunks of 128 + 4 chunks of 160
#define NT   40         // 20 row-tiles x 2 col-halves

typedef unsigned long long ull;

// Split-K partials as (even-k, odd-k) float pairs; reduced+exp'd results
__device__ __align__(16) ull   g_Ep[NS * 2048 * VDIM];   // 14.7 MB
__device__ __align__(16) ull   g_Dp[NS * 512 * VDIM];    // 3.7 MB
__device__ __align__(16) float g_E[2048 * VDIM];         // exp(enc@W^T)
__device__ __align__(16) float g_D[512 * VDIM];          // exp(dec@W^T + b)

__device__ __forceinline__ ull fma2(ull a, ull b, ull c) {
    ull d;
    asm("fma.rn.f32x2 %0, %1, %2, %3;" : "=l"(d) : "l"(a), "l"(b), "l"(c));
    return d;
}
__device__ __forceinline__ void cp8(uint32_t dst, const void* src) {
    asm volatile("cp.async.ca.shared.global [%0], [%1], 8;" :: "r"(dst), "l"(src));
}
#define CP_COMMIT() asm volatile("cp.async.commit_group;")
#define CP_WAIT1()  asm volatile("cp.async.wait_group 1;")

// ---------------------------------------------------------------------------
// Split-K GEMM. Grid 280, 256 thr, 2 CTAs/SM. Tile 128 rows x 64 cols.
// K lives in the f32x2 lanes (even-k in .lo, odd-k in .hi): zero packing movs.
// SMEM layout [kk-pair][row] of 8B pairs: conflict-free with NO padding,
// A buf 2x16x128x8 = 32 KB, W buf 2x16x64x8 = 16 KB -> exactly 48 KB.
// Thread: 8 rows x 4 cols; row_t = warp*2+(lane>>4); col_t = lane&15.
// ---------------------------------------------------------------------------
__global__ __launch_bounds__(256, 2) void joint_gemm(
    const float* __restrict__ enc, const float* __restrict__ dec,
    const float* __restrict__ Wt)
{
    __shared__ __align__(16) ull As[2][16 * 128];   // 32 KB
    __shared__ __align__(16) ull Ws[2][16 * 64];    // 16 KB

    // bid remap: v<120 -> small chunks (s=0..2, K=128); v>=120 -> big (s=3..6, K=160).
    // Wave pairing (v, v+148) colocates one small with one big chunk per SM.
    const int v = blockIdx.x;
    int s, tile;
    if (v < 120) { s = v / 40;          tile = v - s * 40; }
    else         { int w = v - 120; s = 3 + w / 40; tile = w - (s - 3) * 40; }
    const int iters = (s < 3) ? 4 : 5;
    const int k_lo  = (s < 3) ? s * 128 : 384 + (s - 3) * 160;

    const int rt = tile >> 1, ch = tile & 1;
    const bool is_dec = (rt >= 16);
    const float* A = is_dec ? dec : enc;
    const int row0 = (is_dec ? rt - 16 : rt) * 128;
    const int c0   = ch * 64;
    ull* Cp = is_dec ? (g_Dp + s * 512 * VDIM) : (g_Ep + s * 2048 * VDIM);

    const int tid   = threadIdx.x;
    const int lane  = tid & 31;
    const int warp  = tid >> 5;
    const int row_t = warp * 2 + (lane >> 4);
    const int col_t = lane & 15;

    uint32_t sA[2] = { (uint32_t)__cvta_generic_to_shared(&As[0][0]),
                       (uint32_t)__cvta_generic_to_shared(&As[1][0]) };
    uint32_t sW[2] = { (uint32_t)__cvta_generic_to_shared(&Ws[0][0]),
                       (uint32_t)__cvta_generic_to_shared(&Ws[1][0]) };

    // stage k-iter 'it' into buffer b: 2048 A-pairs + 1024 W-pairs, cp.async 8B
    auto stage = [&](int it, int b) {
        const int k0 = k_lo + it * 32;
        #pragma unroll
        for (int st = 0; st < 8; st++) {           // A: pair p of row r
            int idx = tid + st * 256;
            int p = idx & 15, r = idx >> 4;
            cp8(sA[b] + (p * 128 + r) * 8,
                A + (long)(row0 + r) * HDIM + k0 + 2 * p);
        }
        #pragma unroll
        for (int st = 0; st < 4; st++) {           // W: pair p of col c
            int idx = tid + st * 256;
            int p = idx & 15, c = idx >> 4;
            cp8(sW[b] + (p * 64 + c) * 8,
                Wt + (long)(c0 + c) * HDIM + k0 + 2 * p);
        }
    };

    ull acc[8][4];
    #pragma unroll
    for (int i = 0; i < 8; i++)
        #pragma unroll
        for (int j = 0; j < 4; j++) acc[i][j] = 0ull;

    stage(0, 0); CP_COMMIT();
    stage(1, 1); CP_COMMIT();

    for (int it = 0; it < iters; it++) {
        CP_WAIT1();
        __syncthreads();
        const int b = it & 1;
        const ull* Ab = As[b];
        const ull* Wb = Ws[b];

        #pragma unroll
        for (int p = 0; p < 16; p++) {             // kk-pair
            ull a[8], w[4];
            #pragma unroll
            for (int i = 0; i < 8; i++)
                a[i] = Ab[p * 128 + row_t + 16 * i];
            #pragma unroll
            for (int j = 0; j < 4; j++)
                w[j] = Wb[p * 64 + col_t + 16 * j];
            #pragma unroll
            for (int i = 0; i < 8; i++)
                #pragma unroll
                for (int j = 0; j < 4; j++)
                    acc[i][j] = fma2(a[i], w[j], acc[i][j]);
        }
        __syncthreads();
        if (it + 2 < iters) stage(it + 2, b);
        CP_COMMIT();                               // empty groups are legal
    }

    // Store 8-byte (even,odd) partial pairs; reduce kernel folds lo+hi.
    #pragma unroll
    for (int i = 0; i < 8; i++) {
        long r = row0 + row_t + 16 * i;
        #pragma unroll
        for (int j = 0; j < 4; j++)
            Cp[r * VDIM + c0 + col_t + 16 * j] = acc[i][j];
    }
}

// ---------------------------------------------------------------------------
// Sum NS pair-partials (lo+hi), add bias to D, store exp() of the result.
// ---------------------------------------------------------------------------
__global__ __launch_bounds__(256) void reduce_exp(const float* __restrict__ bias)
{
    int idx = blockIdx.x * 256 + threadIdx.x;
    if (idx < 65536) {                 // E: 65536 float4 outputs
        const float4* p = (const float4*)g_Ep;
        float ax = 0.f, ay = 0.f, az = 0.f, aw = 0.f;
        #pragma unroll
        for (int s = 0; s < NS; s++) {
            float4 v0 = p[(long)s * 131072 + idx * 2];
            float4 v1 = p[(long)s * 131072 + idx * 2 + 1];
            ax += v0.x + v0.y; ay += v0.z + v0.w;
            az += v1.x + v1.y; aw += v1.z + v1.w;
        }
        ((float4*)g_E)[idx] = make_float4(__expf(ax), __expf(ay), __expf(az), __expf(aw));
    } else {                           // D: 16384 float4 outputs
        int j = idx - 65536;
        const float4* p = (const float4*)g_Dp;
        float4 bv = ((const float4*)bias)[j & 31];
        float ax = bv.x, ay = bv.y, az = bv.z, aw = bv.w;
        #pragma unroll
        for (int s = 0; s < NS; s++) {
            float4 v0 = p[(long)s * 32768 + j * 2];
            float4 v1 = p[(long)s * 32768 + j * 2 + 1];
            ax += v0.x + v0.y; ay += v0.z + v0.w;
            az += v1.x + v1.y; aw += v1.z + v1.w;
        }
        ((float4*)g_D)[j] = make_float4(__expf(ax), __expf(ay), __expf(az), __expf(aw));
    }
}

// ---------------------------------------------------------------------------
// Softmax: each warp handles 2 consecutive rows (same (b,t), u and u+1):
// one E load serves both. p = expE*expD; warp-reduce sum; scale.
// ---------------------------------------------------------------------------
__global__ __launch_bounds__(256) void softmax_kernel(float* __restrict__ out)
{
    const int warp = threadIdx.x >> 5;
    const int lane = threadIdx.x & 31;
    const int r0 = blockIdx.x * 16 + warp * 2;   // even; r0,r0+1 share bt
    const int bt = r0 >> 6;
    const int b  = r0 >> 14;
    const int u0 = r0 & 63;

    float4 ev = ((const float4*)g_E)[bt * 32 + lane];
    const float4* Dr = (const float4*)g_D + ((b << 6) + u0) * 32;
    float4 d0 = Dr[lane];
    float4 d1 = Dr[32 + lane];

    float p0 = ev.x * d0.x, p1 = ev.y * d0.y, p2 = ev.z * d0.z, p3 = ev.w * d0.w;
    float q0 = ev.x * d1.x, q1 = ev.y * d1.y, q2 = ev.z * d1.z, q3 = ev.w * d1.w;

    float sp = (p0 + p1) + (p2 + p3);
    float sq = (q0 + q1) + (q2 + q3);
    #pragma unroll
    for (int sh = 16; sh > 0; sh >>= 1) {
        sp += __shfl_xor_sync(0xffffffffu, sp, sh);
        sq += __shfl_xor_sync(0xffffffffu, sq, sh);
    }
    float ip = __fdividef(1.0f, sp);
    float iq = __fdividef(1.0f, sq);

    float4* o = (float4*)out + (long)r0 * 32;
    o[lane]      = make_float4(p0 * ip, p1 * ip, p2 * ip, p3 * ip);
    o[32 + lane] = make_float4(q0 * iq, q1 * iq, q2 * iq, q3 * iq);
}

// ---------------------------------------------------------------------------
extern "C" void kernel_launch(void* const* d_in, const int* in_sizes, int n_in,
                              void* d_out, int out_size)
{
    const float* enc = (const float*)d_in[0];  // [8,256,1024]
    const float* dec = (const float*)d_in[1];  // [8,64,1024]
    const float* W   = (const float*)d_in[2];  // [128,1024]
    const float* b   = (const float*)d_in[3];  // [128]
    float* out = (float*)d_out;                // [8,256,64,128]

    joint_gemm<<<280, 256>>>(enc, dec, W);
    reduce_exp<<<320, 256>>>(b);
    softmax_kernel<<<8192, 256>>>(out);
}

// round 8
// speedup vs baseline: 1.2857x; 1.2857x over previous
#include <cuda_runtime.h>
#include <cuda_bf16.h>
#include <cstdint>

#define HDIM 1024
#define VDIM 128
#define NS   7          // K-splits: 3 chunks of 128 + 4 chunks of 160
#define NT   40         // 20 row-tiles x 2 col-halves

typedef unsigned long long ull;

// Split-K partials as (even-k, odd-k) float pairs; reduced+exp'd results
__device__ __align__(16) ull   g_Ep[NS * 2048 * VDIM];   // 14.7 MB
__device__ __align__(16) ull   g_Dp[NS * 512 * VDIM];    // 3.7 MB
__device__ __align__(16) float g_E[2048 * VDIM];         // exp(enc@W^T)
__device__ __align__(16) float g_D[512 * VDIM];          // exp(dec@W^T + b)

__device__ __forceinline__ ull fma2(ull a, ull b, ull c) {
    ull d;
    asm("fma.rn.f32x2 %0, %1, %2, %3;" : "=l"(d) : "l"(a), "l"(b), "l"(c));
    return d;
}

#define A_STR 36   // floats; 144B rows, 16B-aligned float4 staging; read banks +4
#define W_STR 34   // floats; 136B rows, 8B-aligned float2 staging; read banks (2c+2p)%32

// ---------------------------------------------------------------------------
// Split-K GEMM. Grid 280 (2 CTAs/SM, one wave). Tile 128 rows x 64 cols.
// K in f32x2 lanes (even-k .lo, odd-k .hi): A and W both read as natural
// float2 over k -> zero packing MOVs. Row-major smem, conflict-free both ways.
// Thread: 8 rows x 4 cols; row_t = warp*2+(lane>>4); col_t = lane&15.
// ---------------------------------------------------------------------------
__global__ __launch_bounds__(256, 2) void joint_gemm(
    const float* __restrict__ enc, const float* __restrict__ dec,
    const float* __restrict__ Wt)
{
    __shared__ __align__(16) float As[128 * A_STR];  // 18 KB
    __shared__ __align__(16) float Ws[64 * W_STR];   // 8.5 KB

    // bid remap: v<120 -> small chunks (s=0..2, K=128); v>=120 -> big (s=3..6, K=160).
    // Wave pairing (v, v+148) colocates one small with one big chunk per SM.
    const int v = blockIdx.x;
    int s, tile;
    if (v < 120) { s = v / 40;          tile = v - s * 40; }
    else         { int w = v - 120; s = 3 + w / 40; tile = w - (s - 3) * 40; }
    const int iters = (s < 3) ? 4 : 5;
    const int k_lo  = (s < 3) ? s * 128 : 384 + (s - 3) * 160;

    const int rt = tile >> 1, ch = tile & 1;
    const bool is_dec = (rt >= 16);
    const float* A = is_dec ? dec : enc;
    const int row0 = (is_dec ? rt - 16 : rt) * 128;
    const int c0   = ch * 64;
    ull* Cp = is_dec ? (g_Dp + s * 512 * VDIM) : (g_Ep + s * 2048 * VDIM);

    const int tid   = threadIdx.x;
    const int lane  = tid & 31;
    const int warp  = tid >> 5;
    const int row_t = warp * 2 + (lane >> 4);
    const int col_t = lane & 15;

    // Staging address precompute.
    // A: 1024 float4 slots; thread does 4: r = idx>>3, k4 = (idx&7)*4
    const int a_r  = tid >> 3;          // +32 per step (4 steps cover 128 rows)
    const int a_k4 = (tid & 7) << 2;
    // W: 1024 float2 slots; thread does 4: c = idx>>4, kp = idx&15
    const int w_c  = tid >> 4;          // +16 per step (4 steps cover 64 cols)
    const int w_kp = (tid & 15) << 1;

    ull acc[8][4];
    #pragma unroll
    for (int i = 0; i < 8; i++)
        #pragma unroll
        for (int j = 0; j < 4; j++) acc[i][j] = 0ull;

    for (int it = 0; it < iters; it++) {
        const int k0 = k_lo + it * 32;
        // Preload GMEM into regs (overlaps with other warps' compute + sync)
        float4 aReg[4];
        float2 wReg[4];
        #pragma unroll
        for (int st = 0; st < 4; st++)
            aReg[st] = *(const float4*)(A + (long)(row0 + a_r + st * 32) * HDIM + k0 + a_k4);
        #pragma unroll
        for (int st = 0; st < 4; st++)
            wReg[st] = *(const float2*)(Wt + (long)(c0 + w_c + st * 16) * HDIM + k0 + w_kp);

        __syncthreads();                 // previous compute done
        #pragma unroll
        for (int st = 0; st < 4; st++)
            *(float4*)&As[(a_r + st * 32) * A_STR + a_k4] = aReg[st];
        #pragma unroll
        for (int st = 0; st < 4; st++)
            *(float2*)&Ws[(w_c + st * 16) * W_STR + w_kp] = wReg[st];
        __syncthreads();

        #pragma unroll
        for (int p = 0; p < 16; p++) {   // kk-pair
            ull a[8], w[4];
            #pragma unroll
            for (int i = 0; i < 8; i++)
                a[i] = *(const ull*)&As[(row_t + 16 * i) * A_STR + 2 * p];
            #pragma unroll
            for (int j = 0; j < 4; j++)
                w[j] = *(const ull*)&Ws[(col_t + 16 * j) * W_STR + 2 * p];
            #pragma unroll
            for (int i = 0; i < 8; i++)
                #pragma unroll
                for (int j = 0; j < 4; j++)
                    acc[i][j] = fma2(a[i], w[j], acc[i][j]);
        }
    }

    // Store 8-byte (even,odd) partial pairs; reduce kernel folds lo+hi.
    #pragma unroll
    for (int i = 0; i < 8; i++) {
        long r = row0 + row_t + 16 * i;
        #pragma unroll
        for (int j = 0; j < 4; j++)
            Cp[r * VDIM + c0 + col_t + 16 * j] = acc[i][j];
    }
}

// ---------------------------------------------------------------------------
// Sum NS pair-partials (lo+hi), add bias to D, store exp() of the result.
// ---------------------------------------------------------------------------
__global__ __launch_bounds__(256) void reduce_exp(const float* __restrict__ bias)
{
    int idx = blockIdx.x * 256 + threadIdx.x;
    if (idx < 65536) {                 // E: 65536 float4 outputs
        const float4* p = (const float4*)g_Ep;
        float ax = 0.f, ay = 0.f, az = 0.f, aw = 0.f;
        #pragma unroll
        for (int s = 0; s < NS; s++) {
            float4 v0 = p[(long)s * 131072 + idx * 2];
            float4 v1 = p[(long)s * 131072 + idx * 2 + 1];
            ax += v0.x + v0.y; ay += v0.z + v0.w;
            az += v1.x + v1.y; aw += v1.z + v1.w;
        }
        ((float4*)g_E)[idx] = make_float4(__expf(ax), __expf(ay), __expf(az), __expf(aw));
    } else {                           // D: 16384 float4 outputs
        int j = idx - 65536;
        const float4* p = (const float4*)g_Dp;
        float4 bv = ((const float4*)bias)[j & 31];
        float ax = bv.x, ay = bv.y, az = bv.z, aw = bv.w;
        #pragma unroll
        for (int s = 0; s < NS; s++) {
            float4 v0 = p[(long)s * 32768 + j * 2];
            float4 v1 = p[(long)s * 32768 + j * 2 + 1];
            ax += v0.x + v0.y; ay += v0.z + v0.w;
            az += v1.x + v1.y; aw += v1.z + v1.w;
        }
        ((float4*)g_D)[j] = make_float4(__expf(ax), __expf(ay), __expf(az), __expf(aw));
    }
}

// ---------------------------------------------------------------------------
// Softmax: each warp handles 2 consecutive rows (same (b,t), u and u+1):
// one E load serves both. p = expE*expD; warp-reduce sum; scale.
// ---------------------------------------------------------------------------
__global__ __launch_bounds__(256) void softmax_kernel(float* __restrict__ out)
{
    const int warp = threadIdx.x >> 5;
    const int lane = threadIdx.x & 31;
    const int r0 = blockIdx.x * 16 + warp * 2;   // even; r0,r0+1 share bt
    const int bt = r0 >> 6;
    const int b  = r0 >> 14;
    const int u0 = r0 & 63;

    float4 ev = ((const float4*)g_E)[bt * 32 + lane];
    const float4* Dr = (const float4*)g_D + ((b << 6) + u0) * 32;
    float4 d0 = Dr[lane];
    float4 d1 = Dr[32 + lane];

    float p0 = ev.x * d0.x, p1 = ev.y * d0.y, p2 = ev.z * d0.z, p3 = ev.w * d0.w;
    float q0 = ev.x * d1.x, q1 = ev.y * d1.y, q2 = ev.z * d1.z, q3 = ev.w * d1.w;

    float sp = (p0 + p1) + (p2 + p3);
    float sq = (q0 + q1) + (q2 + q3);
    #pragma unroll
    for (int sh = 16; sh > 0; sh >>= 1) {
        sp += __shfl_xor_sync(0xffffffffu, sp, sh);
        sq += __shfl_xor_sync(0xffffffffu, sq, sh);
    }
    float ip = __fdividef(1.0f, sp);
    float iq = __fdividef(1.0f, sq);

    float4* o = (float4*)out + (long)r0 * 32;
    o[lane]      = make_float4(p0 * ip, p1 * ip, p2 * ip, p3 * ip);
    o[32 + lane] = make_float4(q0 * iq, q1 * iq, q2 * iq, q3 * iq);
}

// ---------------------------------------------------------------------------
extern "C" void kernel_launch(void* const* d_in, const int* in_sizes, int n_in,
                              void* d_out, int out_size)
{
    const float* enc = (const float*)d_in[0];  // [8,256,1024]
    const float* dec = (const float*)d_in[1];  // [8,64,1024]
    const float* W   = (const float*)d_in[2];  // [128,1024]
    const float* b   = (const float*)d_in[3];  // [128]
    float* out = (float*)d_out;                // [8,256,64,128]

    joint_gemm<<<280, 256>>>(enc, dec, W);
    reduce_exp<<<320, 256>>>(b);
    softmax_kernel<<<8192, 256>>>(out);
}